// round 1
// baseline (speedup 1.0000x reference)
#include <cuda_runtime.h>
#include <cuda_bf16.h>

// Problem constants (match reference_code)
#define B_   256
#define PER_ 1024
#define NIN_ 256
#define NOUT_ (PER_ - NIN_)
#define K_   32
#define R_   6.0f

// E = B*NIN*K = 2,097,152 ; total output = 8*E float32 elements
#define E_ (B_ * NIN_ * K_)

// d2 computed WITHOUT fma contraction to match plain JAX elementwise ops
__device__ __forceinline__ float dist2_rn(float xi, float yi, float zi,
                                          float xj, float yj, float zj) {
    float dx = __fsub_rn(xi, xj);
    float dy = __fsub_rn(yi, yj);
    float dz = __fsub_rn(zi, zj);
    float s  = __fadd_rn(__fadd_rn(__fmul_rn(dx, dx), __fmul_rn(dy, dy)),
                         __fmul_rn(dz, dz));
    return s;
}

__global__ void __launch_bounds__(NIN_, 1)
mo3enet_knn_kernel(const float* __restrict__ pos, float* __restrict__ out) {
    __shared__ float sx[PER_];
    __shared__ float sy[PER_];
    __shared__ float sz[PER_];

    const int b   = blockIdx.x;
    const int tid = threadIdx.x;          // one thread per target, tid in [0, NIN)

    // Stage this batch's 1024 positions into SMEM (SoA)
    const float* p = pos + (size_t)b * PER_ * 3;
    for (int j = tid; j < PER_; j += NIN_) {
        sx[j] = p[3 * j + 0];
        sy[j] = p[3 * j + 1];
        sz[j] = p[3 * j + 2];
    }
    __syncthreads();

    const int i    = tid;                  // target index within batch (0..NIN-1)
    const float xi = sx[i], yi = sy[i], zi = sz[i];
    const int goff = b * PER_;
    const int base = (b * NIN_ + i) * K_;  // slot base into each E-sized array

    // Output layout (all float32, concatenated in reference return order):
    float* src_ii  = out + (size_t)0 * E_;   // edge_index row 0
    float* tgt_ii  = out + (size_t)1 * E_;   // edge_index row 1
    float* m_ii    = out + (size_t)2 * E_;
    float* dist_ii = out + (size_t)3 * E_;
    float* src_io  = out + (size_t)4 * E_;   // edge_index_inter row 0
    float* tgt_io  = out + (size_t)5 * E_;   // edge_index_inter row 1
    float* m_io    = out + (size_t)6 * E_;
    float* dist_io = out + (size_t)7 * E_;

    // Target column is constant across all K slots for both edge sets
    const float tgtv = (float)(goff + i);
#pragma unroll
    for (int k = 0; k < K_; k++) {
        tgt_ii[base + k] = tgtv;
        tgt_io[base + k] = tgtv;
    }

    // ---- in->in edges: candidates j in [0, NIN), self excluded ----
    {
        int c = 0;
        // pass 1: valid candidates, ascending index, cap K
        for (int j = 0; j < NIN_ && c < K_; j++) {
            if (j == i) continue;
            float d2 = dist2_rn(xi, yi, zi, sx[j], sy[j], sz[j]);
            float d  = sqrtf(d2);
            if (d < R_) {
                src_ii[base + c]  = (float)(goff + j);
                m_ii[base + c]    = 1.0f;
                dist_ii[base + c] = d;
                c++;
            }
        }
        // pass 2: pad with lowest-index INVALID candidates (self counts as invalid)
        for (int j = 0; c < K_ && j < NIN_; j++) {
            bool valid = false;
            if (j != i) {
                float d2 = dist2_rn(xi, yi, zi, sx[j], sy[j], sz[j]);
                valid = (sqrtf(d2) < R_);
            }
            if (!valid) {
                src_ii[base + c]  = (float)(goff + j);
                m_ii[base + c]    = 0.0f;
                dist_ii[base + c] = 0.0f;
                c++;
            }
        }
    }

    // ---- in->out edges: candidates j in [0, NOUT), global index goff+NIN+j ----
    {
        int c = 0;
        for (int j = 0; j < NOUT_ && c < K_; j++) {
            int jj = NIN_ + j;
            float d2 = dist2_rn(xi, yi, zi, sx[jj], sy[jj], sz[jj]);
            float d  = sqrtf(d2);
            if (d < R_) {
                src_io[base + c]  = (float)(goff + NIN_ + j);
                m_io[base + c]    = 1.0f;
                dist_io[base + c] = d;
                c++;
            }
        }
        for (int j = 0; c < K_ && j < NOUT_; j++) {
            int jj = NIN_ + j;
            float d2 = dist2_rn(xi, yi, zi, sx[jj], sy[jj], sz[jj]);
            bool valid = (sqrtf(d2) < R_);
            if (!valid) {
                src_io[base + c]  = (float)(goff + NIN_ + j);
                m_io[base + c]    = 0.0f;
                dist_io[base + c] = 0.0f;
                c++;
            }
        }
    }
}

extern "C" void kernel_launch(void* const* d_in, const int* in_sizes, int n_in,
                              void* d_out, int out_size) {
    const float* pos = (const float*)d_in[0];   // [N, 3] float32
    // d_in[1] = batch (int32), d_in[2] = aux_ind (int32): layout is deterministic
    // from the problem constants, so they are not needed.
    float* out = (float*)d_out;
    mo3enet_knn_kernel<<<B_, NIN_>>>(pos, out);
}

// round 2
// speedup vs baseline: 1.5858x; 1.5858x over previous
#include <cuda_runtime.h>
#include <cuda_bf16.h>

// Problem constants (match reference_code)
#define B_   256
#define PER_ 1024
#define NIN_ 256
#define NOUT_ (PER_ - NIN_)
#define K_   32
#define R_   6.0f

#define E_ (B_ * PER_ / 4 * K_ / 8 * 8)     // B*NIN*K = 2,097,152
#undef E_
#define E_ (B_ * NIN_ * K_)

#define WARPS_PER_BLOCK 8
#define THREADS_ (WARPS_PER_BLOCK * 32)
#define BLOCKS_PER_BATCH (NIN_ / WARPS_PER_BLOCK)   // 32
#define GRID_ (B_ * BLOCKS_PER_BATCH)               // 8192

// distance^2 WITHOUT fma contraction to match plain JAX elementwise ops
__device__ __forceinline__ float dist2_rn(float xi, float yi, float zi,
                                          float xj, float yj, float zj) {
    float dx = __fsub_rn(xi, xj);
    float dy = __fsub_rn(yi, yj);
    float dz = __fsub_rn(zi, zj);
    return __fadd_rn(__fadd_rn(__fmul_rn(dx, dx), __fmul_rn(dy, dy)),
                     __fmul_rn(dz, dz));
}

__global__ void __launch_bounds__(THREADS_, 4)
mo3enet_knn_warp_kernel(const float* __restrict__ pos, float* __restrict__ out) {
    __shared__ float sx[PER_];
    __shared__ float sy[PER_];
    __shared__ float sz[PER_];

    const int b    = blockIdx.x / BLOCKS_PER_BATCH;
    const int grp  = blockIdx.x % BLOCKS_PER_BATCH;
    const int tid  = threadIdx.x;
    const int warp = tid >> 5;
    const int lane = tid & 31;

    // Stage this batch's 1024 positions into SMEM (SoA)
    const float* p = pos + (size_t)b * PER_ * 3;
    for (int j = tid; j < PER_; j += THREADS_) {
        sx[j] = p[3 * j + 0];
        sy[j] = p[3 * j + 1];
        sz[j] = p[3 * j + 2];
    }
    __syncthreads();

    const int i    = grp * WARPS_PER_BLOCK + warp;   // target index within batch
    const float xi = sx[i], yi = sy[i], zi = sz[i];
    const int goff = b * PER_;
    const int base = (b * NIN_ + i) * K_;

    float* src_ii  = out + (size_t)0 * E_;
    float* tgt_ii  = out + (size_t)1 * E_;
    float* m_ii    = out + (size_t)2 * E_;
    float* dist_ii = out + (size_t)3 * E_;
    float* src_io  = out + (size_t)4 * E_;
    float* tgt_io  = out + (size_t)5 * E_;
    float* m_io    = out + (size_t)6 * E_;
    float* dist_io = out + (size_t)7 * E_;

    const unsigned lmask_lt = (1u << lane) - 1u;

    // target column: one coalesced warp-wide store each
    const float tgtv = (float)(goff + i);
    tgt_ii[base + lane] = tgtv;
    tgt_io[base + lane] = tgtv;

    // ================= in -> in  (candidates j in [0,NIN), self excluded) ====
    {
        int c = 0;
        for (int jb = 0; jb < NIN_ && c < K_; jb += 32) {
            int j = jb + lane;
            float d2 = dist2_rn(xi, yi, zi, sx[j], sy[j], sz[j]);
            float d  = sqrtf(d2);
            bool valid = (d < R_) && (j != i);
            unsigned m = __ballot_sync(0xffffffffu, valid);
            int pre = __popc(m & lmask_lt);
            int slot = c + pre;
            if (valid && slot < K_) {
                src_ii[base + slot]  = (float)(goff + j);
                m_ii[base + slot]    = 1.0f;
                dist_ii[base + slot] = d;
            }
            c += __popc(m);
        }
        if (c > K_) c = K_;
        // padding: lowest-index invalid candidates (self counts as invalid)
        for (int jb = 0; jb < NIN_ && c < K_; jb += 32) {
            int j = jb + lane;
            float d2 = dist2_rn(xi, yi, zi, sx[j], sy[j], sz[j]);
            bool invalid = !((sqrtf(d2) < R_) && (j != i));
            unsigned m = __ballot_sync(0xffffffffu, invalid);
            int pre = __popc(m & lmask_lt);
            int slot = c + pre;
            if (invalid && slot < K_) {
                src_ii[base + slot]  = (float)(goff + j);
                m_ii[base + slot]    = 0.0f;
                dist_ii[base + slot] = 0.0f;
            }
            c += __popc(m);
        }
    }

    // ================= in -> out (candidates jj in [NIN,PER)) ===============
    {
        int c = 0;
        for (int jb = 0; jb < NOUT_ && c < K_; jb += 32) {
            int jj = NIN_ + jb + lane;
            float d2 = dist2_rn(xi, yi, zi, sx[jj], sy[jj], sz[jj]);
            float d  = sqrtf(d2);
            bool valid = (d < R_);
            unsigned m = __ballot_sync(0xffffffffu, valid);
            int pre = __popc(m & lmask_lt);
            int slot = c + pre;
            if (valid && slot < K_) {
                src_io[base + slot]  = (float)(goff + jj);
                m_io[base + slot]    = 1.0f;
                dist_io[base + slot] = d;
            }
            c += __popc(m);
        }
        if (c > K_) c = K_;
        for (int jb = 0; jb < NOUT_ && c < K_; jb += 32) {
            int jj = NIN_ + jb + lane;
            float d2 = dist2_rn(xi, yi, zi, sx[jj], sy[jj], sz[jj]);
            bool invalid = !(sqrtf(d2) < R_);
            unsigned m = __ballot_sync(0xffffffffu, invalid);
            int pre = __popc(m & lmask_lt);
            int slot = c + pre;
            if (invalid && slot < K_) {
                src_io[base + slot]  = (float)(goff + jj);
                m_io[base + slot]    = 0.0f;
                dist_io[base + slot] = 0.0f;
            }
            c += __popc(m);
        }
    }
}

extern "C" void kernel_launch(void* const* d_in, const int* in_sizes, int n_in,
                              void* d_out, int out_size) {
    const float* pos = (const float*)d_in[0];   // [N, 3] float32
    float* out = (float*)d_out;
    mo3enet_knn_warp_kernel<<<GRID_, THREADS_>>>(pos, out);
}

// round 3
// speedup vs baseline: 2.7420x; 1.7291x over previous
#include <cuda_runtime.h>
#include <cuda_bf16.h>

// Problem constants (match reference_code)
#define B_    256
#define PER_  1024
#define NIN_  256
#define NOUT_ (PER_ - NIN_)
#define K_    32
#define R2_   36.0f
#define E_    (B_ * NIN_ * K_)      // 2,097,152

#define TPB_  256
#define WPB_  8                      // warps per block
#define BPB_  (NIN_ / WPB_)          // 32 blocks per batch
#define GRID_ (B_ * BPB_)            // 8192

// distance^2 WITHOUT fma contraction to match plain JAX elementwise ops.
// Note: d = sqrt_rn(d2) < 6  <=>  d2 < 36  (correctly-rounded sqrt is monotone,
// sqrt(36)=6 exact), so the validity test needs no sqrt.
__device__ __forceinline__ float dist2_rn(float xi, float yi, float zi, float4 c) {
    float dx = __fsub_rn(xi, c.x);
    float dy = __fsub_rn(yi, c.y);
    float dz = __fsub_rn(zi, c.z);
    return __fadd_rn(__fadd_rn(__fmul_rn(dx, dx), __fmul_rn(dy, dy)),
                     __fmul_rn(dz, dz));
}

__global__ void __launch_bounds__(TPB_, 4)
mo3enet_knn_slot_kernel(const float* __restrict__ pos, float* __restrict__ out) {
    __shared__ float4   sp[PER_];          // 16 KB  batch positions (SoA->AoS4)
    __shared__ unsigned smask[WPB_][32];   // 1 KB   saved validity ballots
    __shared__ float2   sbuf[WPB_][K_];    // 2 KB   per-warp slot buffer {d2, j}

    const int b    = blockIdx.x / BPB_;
    const int grp  = blockIdx.x % BPB_;
    const int tid  = threadIdx.x;
    const int warp = tid >> 5;
    const int lane = tid & 31;

    // Stage this batch's 1024 positions into SMEM as float4
    const float* p = pos + (size_t)b * PER_ * 3;
    for (int j = tid; j < PER_; j += TPB_)
        sp[j] = make_float4(p[3 * j + 0], p[3 * j + 1], p[3 * j + 2], 0.0f);
    __syncthreads();

    const int i    = grp * WPB_ + warp;    // target index within batch
    const float xi = sp[i].x, yi = sp[i].y, zi = sp[i].z;
    const int goff = b * PER_;
    const int base = (b * NIN_ + i) * K_ + lane;   // lane owns slot `lane`
    const unsigned lt = (1u << lane) - 1u;

    // =================== edge set 1: in -> in ===========================
    {
        unsigned cnt = 0;
#pragma unroll
        for (int t = 0; t < NIN_ / 32; t++) {
            int j = t * 32 + lane;
            float d2 = dist2_rn(xi, yi, zi, sp[j]);
            bool valid = (d2 < R2_) && (j != i);
            unsigned m = __ballot_sync(0xffffffffu, valid);
            if (lane == 0) smask[warp][t] = m;
            unsigned slot = cnt + __popc(m & lt);
            if (valid && slot < K_)
                sbuf[warp][slot] = make_float2(d2, __int_as_float(j));
            cnt += __popc(m);
        }
        if (cnt < K_) {   // uniform branch: pad with lowest-index invalids
            unsigned c = cnt;
            for (int t = 0; c < K_; t++) {
                unsigned m = ~smask[warp][t];    // invalid (self included)
                unsigned slot = c + __popc(m & lt);
                if (((m >> lane) & 1u) && slot < K_)
                    sbuf[warp][slot] = make_float2(-1.0f, __int_as_float(t * 32 + lane));
                c += __popc(m);
            }
        }
        __syncwarp();
        float2 v = sbuf[warp][lane];
        int j = __float_as_int(v.y);
        bool val = (v.x >= 0.0f);
        out[0 * E_ + base] = (float)(goff + j);
        out[1 * E_ + base] = (float)(goff + i);
        out[2 * E_ + base] = val ? 1.0f : 0.0f;
        out[3 * E_ + base] = val ? sqrtf(v.x) : 0.0f;
        __syncwarp();   // sbuf reused below
    }

    // =================== edge set 2: in -> out ==========================
    {
        unsigned cnt = 0;
#pragma unroll
        for (int t = 0; t < NOUT_ / 32; t++) {
            int j = NIN_ + t * 32 + lane;
            float d2 = dist2_rn(xi, yi, zi, sp[j]);
            bool valid = (d2 < R2_);
            unsigned m = __ballot_sync(0xffffffffu, valid);
            if (lane == 0) smask[warp][t] = m;
            unsigned slot = cnt + __popc(m & lt);
            if (valid && slot < K_)
                sbuf[warp][slot] = make_float2(d2, __int_as_float(j));
            cnt += __popc(m);
        }
        if (cnt < K_) {
            unsigned c = cnt;
            for (int t = 0; c < K_; t++) {
                unsigned m = ~smask[warp][t];
                unsigned slot = c + __popc(m & lt);
                if (((m >> lane) & 1u) && slot < K_)
                    sbuf[warp][slot] = make_float2(-1.0f, __int_as_float(NIN_ + t * 32 + lane));
                c += __popc(m);
            }
        }
        __syncwarp();
        float2 v = sbuf[warp][lane];
        int j = __float_as_int(v.y);
        bool val = (v.x >= 0.0f);
        out[4 * E_ + base] = (float)(goff + j);
        out[5 * E_ + base] = (float)(goff + i);
        out[6 * E_ + base] = val ? 1.0f : 0.0f;
        out[7 * E_ + base] = val ? sqrtf(v.x) : 0.0f;
    }
}

extern "C" void kernel_launch(void* const* d_in, const int* in_sizes, int n_in,
                              void* d_out, int out_size) {
    const float* pos = (const float*)d_in[0];   // [N, 3] float32
    float* out = (float*)d_out;
    mo3enet_knn_slot_kernel<<<GRID_, TPB_>>>(pos, out);
}

// round 4
// speedup vs baseline: 3.1427x; 1.1461x over previous
#include <cuda_runtime.h>
#include <cuda_bf16.h>

// Problem constants (match reference_code)
#define B_    256
#define PER_  1024
#define NIN_  256
#define NOUT_ (PER_ - NIN_)
#define K_    32
#define E_    (B_ * NIN_ * K_)      // 2,097,152

#define TPB_  256
#define WPB_  8                      // warps per block (8 targets per block)
#define BPB_  (NIN_ / WPB_)          // 32 blocks per batch
#define GRID_ (B_ * BPB_)            // 8192

typedef unsigned long long u64;

// ---- packed f32x2 helpers (per-component .rn == scalar __fadd_rn/__fmul_rn) ----
__device__ __forceinline__ u64 pack2(float lo, float hi) {
    u64 r; asm("mov.b64 %0, {%1, %2};" : "=l"(r) : "f"(lo), "f"(hi)); return r;
}
__device__ __forceinline__ void unpack2(u64 v, float& lo, float& hi) {
    asm("mov.b64 {%0, %1}, %2;" : "=f"(lo), "=f"(hi) : "l"(v));
}
__device__ __forceinline__ u64 add2(u64 a, u64 b) {
    u64 r; asm("add.rn.f32x2 %0, %1, %2;" : "=l"(r) : "l"(a), "l"(b)); return r;
}
__device__ __forceinline__ u64 mul2(u64 a, u64 b) {
    u64 r; asm("mul.rn.f32x2 %0, %1, %2;" : "=l"(r) : "l"(a), "l"(b)); return r;
}

// validity: d = sqrt_rn(d2) < 6  <=>  d2 < 36 (monotone correctly-rounded sqrt,
// sqrt(36)=6 exact) -> no sqrt in the scan.

__global__ void __launch_bounds__(TPB_, 4)
mo3enet_knn_f32x2_kernel(const float* __restrict__ pos, float* __restrict__ out) {
    // NEGATED coords, pair-packed: slot[t*32+l] = { -c[64t+l], -c[64t+32+l] }
    __shared__ u64      snx[PER_ / 2];          // 4 KB
    __shared__ u64      sny[PER_ / 2];          // 4 KB
    __shared__ u64      snz[PER_ / 2];          // 4 KB
    __shared__ unsigned smask[WPB_][32];        // 1 KB  validity ballots (per 32-cand word)
    __shared__ float2   sbuf[WPB_][K_];         // 2 KB  per-warp slots {d2 | -1, j-bits}

    const int b    = blockIdx.x / BPB_;
    const int grp  = blockIdx.x % BPB_;
    const int tid  = threadIdx.x;
    const int warp = tid >> 5;
    const int lane = tid & 31;

    // ---- stage batch positions (negated) into pair-packed SoA ----
    const float* p = pos + (size_t)b * PER_ * 3;
    for (int j = tid; j < PER_; j += TPB_) {
        float x = p[3 * j + 0], y = p[3 * j + 1], z = p[3 * j + 2];
        int idx = ((j >> 6) << 5) + (j & 31);    // pair slot
        int hw  = (j >> 5) & 1;                  // low/high word of pair
        ((float*)snx)[2 * idx + hw] = -x;
        ((float*)sny)[2 * idx + hw] = -y;
        ((float*)snz)[2 * idx + hw] = -z;
    }
    __syncthreads();

    const int i    = grp * WPB_ + warp;          // this warp's target (0..NIN-1)
    const int iidx = ((i >> 6) << 5) + (i & 31);
    const int ihw  = (i >> 5) & 1;
    const float xi = -((float*)snx)[2 * iidx + ihw];
    const float yi = -((float*)sny)[2 * iidx + ihw];
    const float zi = -((float*)snz)[2 * iidx + ihw];
    const u64 xi2 = pack2(xi, xi);
    const u64 yi2 = pack2(yi, yi);
    const u64 zi2 = pack2(zi, zi);

    const int goff = b * PER_;
    const int base = (b * NIN_ + i) * K_ + lane;  // lane owns slot `lane`
    const unsigned lt = (1u << lane) - 1u;
    const float tgtv = (float)(goff + i);

    // ==================== edge set 1: in -> in (j in [0,256)) ================
    {
        unsigned cnt = 0;
#pragma unroll
        for (int t = 0; t < NIN_ / 64; t++) {
            u64 dx = add2(xi2, snx[t * 32 + lane]);
            u64 dy = add2(yi2, sny[t * 32 + lane]);
            u64 dz = add2(zi2, snz[t * 32 + lane]);
            u64 s  = add2(add2(mul2(dx, dx), mul2(dy, dy)), mul2(dz, dz));
            float d2lo, d2hi; unpack2(s, d2lo, d2hi);
            int j0 = t * 64 + lane;
            int j1 = t * 64 + 32 + lane;
            bool v0 = (d2lo < 36.0f) && (j0 != i);
            bool v1 = (d2hi < 36.0f) && (j1 != i);
            unsigned m0 = __ballot_sync(0xffffffffu, v0);
            unsigned m1 = __ballot_sync(0xffffffffu, v1);
            if (lane == 0)
                *(u64*)&smask[warp][2 * t] = ((u64)m1 << 32) | (u64)m0;
            unsigned s0 = cnt + __popc(m0 & lt);
            if (v0 && s0 < K_) sbuf[warp][s0] = make_float2(d2lo, __int_as_float(j0));
            cnt += __popc(m0);
            unsigned s1 = cnt + __popc(m1 & lt);
            if (v1 && s1 < K_) sbuf[warp][s1] = make_float2(d2hi, __int_as_float(j1));
            cnt += __popc(m1);
        }
        if (cnt < K_) {   // warp-uniform: pad with lowest-index invalids
            unsigned c = cnt;
            for (int w = 0; c < K_; w++) {
                unsigned m = ~smask[warp][w];
                unsigned sl = c + __popc(m & lt);
                if (((m >> lane) & 1u) && sl < K_)
                    sbuf[warp][sl] = make_float2(-1.0f, __int_as_float(32 * w + lane));
                c += __popc(m);
            }
        }
        __syncwarp();
        float2 v = sbuf[warp][lane];
        int j = __float_as_int(v.y);
        bool val = (v.x >= 0.0f);
        out[0 * E_ + base] = (float)(goff + j);
        out[1 * E_ + base] = tgtv;
        out[2 * E_ + base] = val ? 1.0f : 0.0f;
        out[3 * E_ + base] = val ? sqrtf(v.x) : 0.0f;
        __syncwarp();   // sbuf reused below
    }

    // ==================== edge set 2: in -> out (j in [256,1024)) ============
    {
        unsigned cnt = 0;
#pragma unroll
        for (int t = 0; t < NOUT_ / 64; t++) {
            int ps = (NIN_ / 2) + t * 32 + lane;   // pair slot offset for outs
            u64 dx = add2(xi2, snx[ps]);
            u64 dy = add2(yi2, sny[ps]);
            u64 dz = add2(zi2, snz[ps]);
            u64 s  = add2(add2(mul2(dx, dx), mul2(dy, dy)), mul2(dz, dz));
            float d2lo, d2hi; unpack2(s, d2lo, d2hi);
            int j0 = NIN_ + t * 64 + lane;
            int j1 = NIN_ + t * 64 + 32 + lane;
            bool v0 = (d2lo < 36.0f);
            bool v1 = (d2hi < 36.0f);
            unsigned m0 = __ballot_sync(0xffffffffu, v0);
            unsigned m1 = __ballot_sync(0xffffffffu, v1);
            if (lane == 0)
                *(u64*)&smask[warp][2 * t] = ((u64)m1 << 32) | (u64)m0;
            unsigned s0 = cnt + __popc(m0 & lt);
            if (v0 && s0 < K_) sbuf[warp][s0] = make_float2(d2lo, __int_as_float(j0));
            cnt += __popc(m0);
            unsigned s1 = cnt + __popc(m1 & lt);
            if (v1 && s1 < K_) sbuf[warp][s1] = make_float2(d2hi, __int_as_float(j1));
            cnt += __popc(m1);
        }
        if (cnt < K_) {
            unsigned c = cnt;
            for (int w = 0; c < K_; w++) {
                unsigned m = ~smask[warp][w];
                unsigned sl = c + __popc(m & lt);
                if (((m >> lane) & 1u) && sl < K_)
                    sbuf[warp][sl] = make_float2(-1.0f, __int_as_float(NIN_ + 32 * w + lane));
                c += __popc(m);
            }
        }
        __syncwarp();
        float2 v = sbuf[warp][lane];
        int j = __float_as_int(v.y);
        bool val = (v.x >= 0.0f);
        out[4 * E_ + base] = (float)(goff + j);
        out[5 * E_ + base] = tgtv;
        out[6 * E_ + base] = val ? 1.0f : 0.0f;
        out[7 * E_ + base] = val ? sqrtf(v.x) : 0.0f;
    }
}

extern "C" void kernel_launch(void* const* d_in, const int* in_sizes, int n_in,
                              void* d_out, int out_size) {
    const float* pos = (const float*)d_in[0];   // [N, 3] float32
    float* out = (float*)d_out;
    mo3enet_knn_f32x2_kernel<<<GRID_, TPB_>>>(pos, out);
}

// round 5
// speedup vs baseline: 3.7003x; 1.1774x over previous
#include <cuda_runtime.h>
#include <cuda_bf16.h>

// Problem constants (match reference_code)
#define B_    256
#define PER_  1024
#define NIN_  256
#define NOUT_ (PER_ - NIN_)
#define K_    32
#define E_    (B_ * NIN_ * K_)      // 2,097,152

#define TPB_  256
#define WPB_  8                      // warps per block
#define TGT_PER_WARP 2
#define TGT_PER_BLOCK (WPB_ * TGT_PER_WARP)    // 16
#define BPB_  (NIN_ / TGT_PER_BLOCK)           // 16 blocks per batch
#define GRID_ (B_ * BPB_)                      // 4096

typedef unsigned long long u64;

// ---- packed f32x2 helpers ----
__device__ __forceinline__ u64 pack2(float lo, float hi) {
    u64 r; asm("mov.b64 %0, {%1, %2};" : "=l"(r) : "f"(lo), "f"(hi)); return r;
}
__device__ __forceinline__ void unpack2(u64 v, float& lo, float& hi) {
    asm("mov.b64 {%0, %1}, %2;" : "=f"(lo), "=f"(hi) : "l"(v));
}
__device__ __forceinline__ u64 add2(u64 a, u64 b) {
    u64 r; asm("add.rn.f32x2 %0, %1, %2;" : "=l"(r) : "l"(a), "l"(b)); return r;
}
__device__ __forceinline__ u64 mul2(u64 a, u64 b) {
    u64 r; asm("mul.rn.f32x2 %0, %1, %2;" : "=l"(r) : "l"(a), "l"(b)); return r;
}
__device__ __forceinline__ u64 fma2(u64 a, u64 b, u64 c) {
    u64 r; asm("fma.rn.f32x2 %0, %1, %2, %3;" : "=l"(r) : "l"(a), "l"(b), "l"(c)); return r;
}

// validity: d = sqrt(d2) < 6  <=>  d2 < 36 (monotone sqrt, sqrt(36)=6 exact)

__global__ void __launch_bounds__(TPB_, 4)
mo3enet_knn_dual_kernel(const float* __restrict__ pos, float* __restrict__ out) {
    // NEGATED coords, pair-packed: slot[(j>>6)*32 + (j&31)] word[(j>>5)&1] = -c[j]
    __shared__ u64      snx[PER_ / 2];            // 4 KB
    __shared__ u64      sny[PER_ / 2];            // 4 KB
    __shared__ u64      snz[PER_ / 2];            // 4 KB
    __shared__ unsigned smask[WPB_][TGT_PER_WARP][32];   // 2 KB ballots
    __shared__ float2   sbuf[WPB_][TGT_PER_WARP][64];    // 8 KB slots {d2|-1, j}

    const int b    = blockIdx.x / BPB_;
    const int grp  = blockIdx.x % BPB_;
    const int tid  = threadIdx.x;
    const int warp = tid >> 5;
    const int lane = tid & 31;

    // ---- stage batch positions (negated) into pair-packed SoA ----
    const float* p = pos + (size_t)b * PER_ * 3;
    for (int j = tid; j < PER_; j += TPB_) {
        float x = p[3 * j + 0], y = p[3 * j + 1], z = p[3 * j + 2];
        int idx = ((j >> 6) << 5) + (j & 31);
        int hw  = (j >> 5) & 1;
        ((float*)snx)[2 * idx + hw] = -x;
        ((float*)sny)[2 * idx + hw] = -y;
        ((float*)snz)[2 * idx + hw] = -z;
    }
    __syncthreads();

    // this warp's two targets
    const int iA = grp * TGT_PER_BLOCK + warp * TGT_PER_WARP;
    const int iB = iA + 1;
    const int goff = b * PER_;
    const unsigned lt = (1u << lane) - 1u;

    u64 xiA2, yiA2, ziA2, xiB2, yiB2, ziB2;
    {
        int ia = ((iA >> 6) << 5) + (iA & 31), ha = (iA >> 5) & 1;
        float xa = -((float*)snx)[2 * ia + ha];
        float ya = -((float*)sny)[2 * ia + ha];
        float za = -((float*)snz)[2 * ia + ha];
        int ib = ((iB >> 6) << 5) + (iB & 31), hb = (iB >> 5) & 1;
        float xb = -((float*)snx)[2 * ib + hb];
        float yb = -((float*)sny)[2 * ib + hb];
        float zb = -((float*)snz)[2 * ib + hb];
        xiA2 = pack2(xa, xa); yiA2 = pack2(ya, ya); ziA2 = pack2(za, za);
        xiB2 = pack2(xb, xb); yiB2 = pack2(yb, yb); ziB2 = pack2(zb, zb);
    }

    const int baseA = (b * NIN_ + iA) * K_ + lane;
    const int baseB = (b * NIN_ + iB) * K_ + lane;

    // ==================== edge set 1: in -> in (j in [0,256)) ================
    {
        unsigned cntA = 0, cntB = 0;
#pragma unroll
        for (int t = 0; t < NIN_ / 64; t++) {
            u64 cx = snx[t * 32 + lane];
            u64 cy = sny[t * 32 + lane];
            u64 cz = snz[t * 32 + lane];
            const int j0 = t * 64 + lane;
            const int j1 = t * 64 + 32 + lane;
            // target A
            {
                u64 dx = add2(xiA2, cx), dy = add2(yiA2, cy), dz = add2(ziA2, cz);
                u64 s  = fma2(dx, dx, fma2(dy, dy, mul2(dz, dz)));
                float lo, hi; unpack2(s, lo, hi);
                bool v0 = (lo < 36.0f) && (j0 != iA);
                bool v1 = (hi < 36.0f) && (j1 != iA);
                unsigned m0 = __ballot_sync(0xffffffffu, v0);
                unsigned m1 = __ballot_sync(0xffffffffu, v1);
                if (lane == 0)
                    *(u64*)&smask[warp][0][2 * t] = ((u64)m1 << 32) | (u64)m0;
                unsigned s0 = min(cntA + __popc(m0 & lt), 63u);
                if (v0) sbuf[warp][0][s0] = make_float2(lo, __int_as_float(j0));
                cntA += __popc(m0);
                unsigned s1 = min(cntA + __popc(m1 & lt), 63u);
                if (v1) sbuf[warp][0][s1] = make_float2(hi, __int_as_float(j1));
                cntA += __popc(m1);
            }
            // target B
            {
                u64 dx = add2(xiB2, cx), dy = add2(yiB2, cy), dz = add2(ziB2, cz);
                u64 s  = fma2(dx, dx, fma2(dy, dy, mul2(dz, dz)));
                float lo, hi; unpack2(s, lo, hi);
                bool v0 = (lo < 36.0f) && (j0 != iB);
                bool v1 = (hi < 36.0f) && (j1 != iB);
                unsigned m0 = __ballot_sync(0xffffffffu, v0);
                unsigned m1 = __ballot_sync(0xffffffffu, v1);
                if (lane == 0)
                    *(u64*)&smask[warp][1][2 * t] = ((u64)m1 << 32) | (u64)m0;
                unsigned s0 = min(cntB + __popc(m0 & lt), 63u);
                if (v0) sbuf[warp][1][s0] = make_float2(lo, __int_as_float(j0));
                cntB += __popc(m0);
                unsigned s1 = min(cntB + __popc(m1 & lt), 63u);
                if (v1) sbuf[warp][1][s1] = make_float2(hi, __int_as_float(j1));
                cntB += __popc(m1);
            }
        }
        // padding + emit, per target (warp-uniform control)
#pragma unroll
        for (int T = 0; T < 2; T++) {
            unsigned cnt = T ? cntB : cntA;
            if (cnt < K_) {
                unsigned c = cnt;
                for (int w = 0; c < K_; w++) {
                    unsigned m = ~smask[warp][T][w];
                    unsigned sl = c + __popc(m & lt);
                    if (((m >> lane) & 1u) && sl < K_)
                        sbuf[warp][T][sl] = make_float2(-1.0f, __int_as_float(32 * w + lane));
                    c += __popc(m);
                }
            }
            __syncwarp();
            float2 v = sbuf[warp][T][lane];
            int j = __float_as_int(v.y);
            bool val = (v.x >= 0.0f);
            int base = T ? baseB : baseA;
            out[0 * E_ + base] = (float)(goff + j);
            out[1 * E_ + base] = (float)(goff + (T ? iB : iA));
            out[2 * E_ + base] = val ? 1.0f : 0.0f;
            out[3 * E_ + base] = val ? sqrtf(v.x) : 0.0f;
        }
        __syncwarp();   // sbuf/smask reused below
    }

    // ==================== edge set 2: in -> out (j in [256,1024)) ============
    {
        unsigned cntA = 0, cntB = 0;
#pragma unroll
        for (int t = 0; t < NOUT_ / 64; t++) {
            int ps = (NIN_ / 2) + t * 32 + lane;
            u64 cx = snx[ps];
            u64 cy = sny[ps];
            u64 cz = snz[ps];
            const int j0 = NIN_ + t * 64 + lane;
            const int j1 = NIN_ + t * 64 + 32 + lane;
            // target A
            {
                u64 dx = add2(xiA2, cx), dy = add2(yiA2, cy), dz = add2(ziA2, cz);
                u64 s  = fma2(dx, dx, fma2(dy, dy, mul2(dz, dz)));
                float lo, hi; unpack2(s, lo, hi);
                bool v0 = (lo < 36.0f);
                bool v1 = (hi < 36.0f);
                unsigned m0 = __ballot_sync(0xffffffffu, v0);
                unsigned m1 = __ballot_sync(0xffffffffu, v1);
                if (lane == 0)
                    *(u64*)&smask[warp][0][2 * t] = ((u64)m1 << 32) | (u64)m0;
                unsigned s0 = min(cntA + __popc(m0 & lt), 63u);
                if (v0) sbuf[warp][0][s0] = make_float2(lo, __int_as_float(j0));
                cntA += __popc(m0);
                unsigned s1 = min(cntA + __popc(m1 & lt), 63u);
                if (v1) sbuf[warp][0][s1] = make_float2(hi, __int_as_float(j1));
                cntA += __popc(m1);
            }
            // target B
            {
                u64 dx = add2(xiB2, cx), dy = add2(yiB2, cy), dz = add2(ziB2, cz);
                u64 s  = fma2(dx, dx, fma2(dy, dy, mul2(dz, dz)));
                float lo, hi; unpack2(s, lo, hi);
                bool v0 = (lo < 36.0f);
                bool v1 = (hi < 36.0f);
                unsigned m0 = __ballot_sync(0xffffffffu, v0);
                unsigned m1 = __ballot_sync(0xffffffffu, v1);
                if (lane == 0)
                    *(u64*)&smask[warp][1][2 * t] = ((u64)m1 << 32) | (u64)m0;
                unsigned s0 = min(cntB + __popc(m0 & lt), 63u);
                if (v0) sbuf[warp][1][s0] = make_float2(lo, __int_as_float(j0));
                cntB += __popc(m0);
                unsigned s1 = min(cntB + __popc(m1 & lt), 63u);
                if (v1) sbuf[warp][1][s1] = make_float2(hi, __int_as_float(j1));
                cntB += __popc(m1);
            }
        }
#pragma unroll
        for (int T = 0; T < 2; T++) {
            unsigned cnt = T ? cntB : cntA;
            if (cnt < K_) {
                unsigned c = cnt;
                for (int w = 0; c < K_; w++) {
                    unsigned m = ~smask[warp][T][w];
                    unsigned sl = c + __popc(m & lt);
                    if (((m >> lane) & 1u) && sl < K_)
                        sbuf[warp][T][sl] = make_float2(-1.0f, __int_as_float(NIN_ + 32 * w + lane));
                    c += __popc(m);
                }
            }
            __syncwarp();
            float2 v = sbuf[warp][T][lane];
            int j = __float_as_int(v.y);
            bool val = (v.x >= 0.0f);
            int base = T ? baseB : baseA;
            out[4 * E_ + base] = (float)(goff + j);
            out[5 * E_ + base] = (float)(goff + (T ? iB : iA));
            out[6 * E_ + base] = val ? 1.0f : 0.0f;
            out[7 * E_ + base] = val ? sqrtf(v.x) : 0.0f;
        }
    }
}

extern "C" void kernel_launch(void* const* d_in, const int* in_sizes, int n_in,
                              void* d_out, int out_size) {
    const float* pos = (const float*)d_in[0];   // [N, 3] float32
    float* out = (float*)d_out;
    mo3enet_knn_dual_kernel<<<GRID_, TPB_>>>(pos, out);
}